// round 7
// baseline (speedup 1.0000x reference)
#include <cuda_runtime.h>
#include <cstdint>

#define BATCH 4
#define TSEQ  512
#define HID   128
#define LOG2E 1.4426950408889634f

// ---------------- scratch (no allocation allowed) ---------------------------
__device__ float g_xg [BATCH * TSEQ * 4 * HID];   // reused by both LSTMs
__device__ float g_Hsh[BATCH * TSEQ * HID];
__device__ float g_A  [BATCH * TSEQ * HID];
__device__ float g_C  [BATCH * TSEQ * HID];
__device__ float g_R  [BATCH * TSEQ * HID];

// ---------------- helpers ----------------------------------------------------
__device__ __forceinline__ float ex2f(float x){ float y; asm("ex2.approx.f32 %0, %1;" : "=f"(y) : "f"(x)); return y; }
__device__ __forceinline__ float rcpf(float x){ float y; asm("rcp.approx.f32 %0, %1;" : "=f"(y) : "f"(x)); return y; }
__device__ __forceinline__ float sigf(float x){ return rcpf(1.0f + ex2f(-LOG2E * x)); }
__device__ __forceinline__ float tanhf_fast(float x){
    return fmaf(-2.0f, rcpf(1.0f + ex2f(2.0f * LOG2E * x)), 1.0f);
}
__device__ __forceinline__ double fma2(double a, double b, double c){
    double d; asm("fma.rn.f32x2 %0, %1, %2, %3;" : "=d"(d) : "d"(a), "d"(b), "d"(c)); return d;
}
__device__ __forceinline__ uint32_t smem_u32(const void* p){
    uint32_t a; asm("{ .reg .u64 t; cvta.to.shared.u64 t, %1; cvt.u32.u64 %0, t; }" : "=r"(a) : "l"(p)); return a;
}
__device__ __forceinline__ uint32_t mapa32(uint32_t a, uint32_t r){
    uint32_t d; asm("mapa.shared::cluster.u32 %0, %1, %2;" : "=r"(d) : "r"(a), "r"(r)); return d;
}
__device__ __forceinline__ uint32_t ctarank(){
    uint32_t r; asm("mov.u32 %0, %%cluster_ctarank;" : "=r"(r)); return r;
}
__device__ __forceinline__ void mbar_init(uint32_t a, uint32_t cnt){
    asm volatile("mbarrier.init.shared.b64 [%0], %1;" :: "r"(a), "r"(cnt) : "memory");
}
__device__ __forceinline__ void mbar_expect(uint32_t a, uint32_t tx){
    asm volatile("mbarrier.arrive.expect_tx.shared.b64 _, [%0], %1;" :: "r"(a), "r"(tx) : "memory");
}
__device__ __forceinline__ void mbar_wait(uint32_t mb, uint32_t phase){
    asm volatile(
        "{\n\t.reg .pred P;\n\t"
        "W_%=:\n\t"
        "mbarrier.try_wait.parity.acquire.cluster.shared::cta.b64 P, [%0], %1, 0x989680;\n\t"
        "@P bra.uni D_%=;\n\t"
        "bra.uni W_%=;\n\t"
        "D_%=:\n\t}"
        :: "r"(mb), "r"(phase) : "memory");
}
__device__ __forceinline__ void st_async32(uint32_t daddr, uint32_t dmbar, float v){
    asm volatile("st.async.shared::cluster.mbarrier::complete_tx::bytes.b32 [%0], %1, [%2];"
        :: "r"(daddr), "r"(__float_as_uint(v)), "r"(dmbar) : "memory");
}
__device__ __forceinline__ void cluster_sync_(){
    asm volatile("barrier.cluster.arrive.aligned;" ::: "memory");
    asm volatile("barrier.cluster.wait.aligned;" ::: "memory");
}

// ============================================================================
// LSTM: 2-CTA cluster per batch. CTA rank owns hidden units [64r, 64r+64)
// (all 4 gates = 256 weight rows, fully register-resident, f32x2 math).
// Per step the 64 new h values are pushed to BOTH CTAs (self + peer) via
// st.async into double-buffered hsm, with ping-pong tx-mbarriers
// (expect 512 bytes = 128 floats per step). Exactly one __syncthreads and
// one mbarrier wait per step. h is read via LDS.128 (double2) to minimize
// issue slots on the serial dot.
// ============================================================================
__global__ __cluster_dims__(2,1,1) __launch_bounds__(512,1)
void lstm_kernel(const float* __restrict__ xg,   // [B,T,512] (bias pre-added)
                 const float* __restrict__ Whh,  // [512,128]
                 float* __restrict__ Hout)       // [B,T,128]
{
    __shared__ __align__(16) float hsm[2][HID];
    __shared__ __align__(16) float gsm[2][256];
    __shared__ __align__(8) unsigned long long mbar[2];

    const int tid  = threadIdx.x;
    const int b    = blockIdx.x >> 1;
    const uint32_t rank = ctarank();
    const int row_l = tid >> 1;          // 0..255 local row
    const int half  = tid & 1;           // which 64 columns of the dot
    const int q     = row_l >> 6;        // gate index (i,f,g,o)
    const int j     = row_l & 63;        // local unit
    const int grow  = q * 128 + (int)rank * 64 + j;   // row in [0,512)

    // 64 weight floats as 32 f32x2 pairs (row base is 256B-aligned)
    double w[32];
    const double* wp = (const double*)(Whh + (size_t)grow * HID + half * 64);
#pragma unroll
    for (int i = 0; i < 32; ++i) w[i] = wp[i];

    if (tid < HID) { hsm[0][tid] = 0.0f; hsm[1][tid] = 0.0f; }

    const uint32_t mb = smem_u32(&mbar[0]);
    const uint32_t hb = smem_u32(&hsm[0][0]);
    if (tid == 0) {
        mbar_init(mb, 1); mbar_init(mb + 8, 1);
        asm volatile("fence.mbarrier_init.release.cluster;" ::: "memory");
        mbar_expect(mb, 512); mbar_expect(mb + 8, 512);
    }
    __syncthreads();
    cluster_sync_();   // all inits visible before any st.async lands

    const int gu = (int)rank * 64 + tid;           // valid for tid<64
    uint32_t dsth[2][2], dstm[2][2];               // [buffer][target rank]
    if (tid < 64) {
#pragma unroll
        for (int d = 0; d < 2; ++d) {
            dsth[0][d] = mapa32(hb + (uint32_t)gu * 4u, (uint32_t)d);
            dsth[1][d] = mapa32(hb + (uint32_t)(HID + gu) * 4u, (uint32_t)d);
            dstm[0][d] = mapa32(mb,     (uint32_t)d);
            dstm[1][d] = mapa32(mb + 8, (uint32_t)d);
        }
    }

    const float* xb = xg + (size_t)b * TSEQ * 512;
    float xv = 0.0f, nv = 0.0f;
    if (!half) xv = __ldg(xb + grow);              // step-0 input projection
    float c = 0.0f;
    int ph0 = 0, ph1 = 0;

    for (int t = 0; t < TSEQ; ++t) {
        if (!half && t + 1 < TSEQ)                  // prefetch next xg
            nv = __ldg(xb + (size_t)(t + 1) * 512 + grow);

        const int par = t & 1;
        if (t > 0) {
            const uint32_t m = mb + (uint32_t)par * 8u;
            mbar_wait(m, par ? (uint32_t)ph1 : (uint32_t)ph0);
            if (par) ph1 ^= 1; else ph0 ^= 1;
            if (tid == 0) mbar_expect(m, 512);      // re-arm for step t+2
        }

        // dot(row, h_prev): LDS.128 h loads + f32x2 FMAs
        const double2* hp = (const double2*)(&hsm[par][half * 64]);
        double a0 = 0.0, a1 = 0.0;
#pragma unroll
        for (int i = 0; i < 16; ++i) {
            const double2 hv = hp[i];
            a0 = fma2(w[2 * i],     hv.x, a0);
            a1 = fma2(w[2 * i + 1], hv.y, a1);
        }
        long long l0 = __double_as_longlong(a0), l1 = __double_as_longlong(a1);
        float s = (__uint_as_float((unsigned)l0) + __uint_as_float((unsigned)(l0 >> 32)))
                + (__uint_as_float((unsigned)l1) + __uint_as_float((unsigned)(l1 >> 32)));
        s += __shfl_xor_sync(0xffffffffu, s, 1);    // combine the two halves
        if (!half) gsm[par][row_l] = s + xv;        // xg folded in here
        __syncthreads();

        if (tid < 64) {
            const float gi = gsm[par][tid];
            const float gf = gsm[par][64 + tid];
            const float gg = gsm[par][128 + tid];
            const float go = gsm[par][192 + tid];
            c = sigf(gf) * c + sigf(gi) * tanhf_fast(gg);
            const float h = sigf(go) * tanhf_fast(c);
            Hout[((size_t)b * TSEQ + t) * HID + gu] = h;
            if (t + 1 < TSEQ) {
                const int wb = par ^ 1;
                st_async32(dsth[wb][0], dstm[wb][0], h);   // self
                st_async32(dsth[wb][1], dstm[wb][1], h);   // peer
            }
        }
        xv = nv;
    }
    cluster_sync_();   // no early exit while peer st.async may be in flight
}

// ============================================================================
// Generic tiled GEMM (K fixed = 128 per operand pair):
//   C[M,N] = scale * (A1@B1 (+ A2@B2) + bias)
// bt=1: B stored [N,K] row-major (x @ W^T); bt=0: B stored [K,N].
// ============================================================================
__global__ void __launch_bounds__(256)
gemm_kernel(const float* __restrict__ A1, const float* __restrict__ B1,
            const float* __restrict__ A2, const float* __restrict__ B2,
            const float* __restrict__ bias, float* __restrict__ Co,
            int N, int ldb, int bt, float scale)
{
    __shared__ float As[16][68];
    __shared__ float Bs[16][68];
    const int tid = threadIdx.x;
    const int m0 = blockIdx.x * 64;
    const int n0 = blockIdx.y * 64;
    const int tx = tid & 15, ty = tid >> 4;

    float acc[4][4];
#pragma unroll
    for (int i = 0; i < 4; ++i)
#pragma unroll
        for (int jj = 0; jj < 4; ++jj) acc[i][jj] = 0.0f;

    for (int pair = 0; pair < 2; ++pair) {
        const float* A = pair ? A2 : A1;
        const float* B = pair ? B2 : B1;
        if (A == nullptr) break;
        for (int kc = 0; kc < 128; kc += 16) {
#pragma unroll
            for (int i = 0; i < 4; ++i) {
                int id = i * 256 + tid;
                int k = id & 15, m = id >> 4;
                As[k][m] = A[(size_t)(m0 + m) * 128 + kc + k];
            }
#pragma unroll
            for (int i = 0; i < 4; ++i) {
                int id = i * 256 + tid;
                if (bt) { int k = id & 15, n = id >> 4;
                    Bs[k][n] = B[(size_t)(n0 + n) * ldb + kc + k];
                } else {  int n = id & 63, k = id >> 6;
                    Bs[k][n] = B[(size_t)(kc + k) * ldb + n0 + n];
                }
            }
            __syncthreads();
#pragma unroll
            for (int k = 0; k < 16; ++k) {
                float av[4], bv[4];
#pragma unroll
                for (int i = 0; i < 4; ++i) av[i] = As[k][ty * 4 + i];
#pragma unroll
                for (int jj = 0; jj < 4; ++jj) bv[jj] = Bs[k][tx * 4 + jj];
#pragma unroll
                for (int i = 0; i < 4; ++i)
#pragma unroll
                    for (int jj = 0; jj < 4; ++jj)
                        acc[i][jj] = fmaf(av[i], bv[jj], acc[i][jj]);
            }
            __syncthreads();
        }
    }
#pragma unroll
    for (int i = 0; i < 4; ++i) {
        const size_t ro = (size_t)(m0 + ty * 4 + i) * N + n0 + tx * 4;
#pragma unroll
        for (int jj = 0; jj < 4; ++jj) {
            float bv = bias ? bias[n0 + tx * 4 + jj] : 0.0f;
            Co[ro + jj] = scale * (acc[i][jj] + bv);
        }
    }
}

// ============================================================================
// Attention: scores -> softmax -> R, fused. Block = (batch, 8 t-rows),
// 256 threads (warp w <-> t-row). A,C pre-scaled by 2*log2e, so
// score_eff[t,s] = -2 * sum_h u[h] * rcp(1 + ex2(A[t,h] + C[s,h]))
// (the sum_h u[h] constant and bu cancel in softmax over s).
// ============================================================================
__global__ void __launch_bounds__(256)
attn_kernel(const float* __restrict__ Ax, const float* __restrict__ Cx,
            const float* __restrict__ Hsh, const float* __restrict__ u,
            float* __restrict__ R)
{
    __shared__ float Asm[8 * 128];
    __shared__ float usm[128];
    __shared__ __align__(16) float tile[32 * 129];
    __shared__ float sc[8 * 512];

    const int tid = threadIdx.x;
    const int wid = tid >> 5, lane = tid & 31;
    const int b = blockIdx.x >> 6;
    const int t0 = (blockIdx.x & 63) * 8;
    const size_t boff = (size_t)b * TSEQ * HID;

#pragma unroll
    for (int i = 0; i < 4; ++i) {
        int id = i * 256 + tid;
        Asm[id] = Ax[boff + (size_t)(t0 + (id >> 7)) * HID + (id & 127)];
    }
    if (tid < 128) usm[tid] = u[tid];
    __syncthreads();

    // ---- scores ----
    const float* arow = &Asm[wid * 128];
    for (int st = 0; st < 16; ++st) {
#pragma unroll
        for (int i = 0; i < 16; ++i) {
            int id = i * 256 + tid;
            int s = id >> 7, h = id & 127;
            tile[s * 129 + h] = Cx[boff + (size_t)(st * 32 + s) * HID + h];
        }
        __syncthreads();
        const float* crow = &tile[lane * 129];
        float su = 0.0f;
#pragma unroll 8
        for (int h = 0; h < 128; ++h)
            su += usm[h] * rcpf(1.0f + ex2f(arow[h] + crow[h]));
        sc[wid * 512 + st * 32 + lane] = -2.0f * su;
        __syncthreads();
    }

    // ---- softmax (per warp over its private t-row) ----
    float m = -1e30f;
#pragma unroll
    for (int i = 0; i < 16; ++i) m = fmaxf(m, sc[wid * 512 + i * 32 + lane]);
#pragma unroll
    for (int o = 16; o > 0; o >>= 1) m = fmaxf(m, __shfl_xor_sync(0xffffffffu, m, o));
    float sum = 0.0f;
#pragma unroll
    for (int i = 0; i < 16; ++i) {
        int idx = wid * 512 + i * 32 + lane;
        float e = ex2f(LOG2E * (sc[idx] - m));
        sc[idx] = e; sum += e;
    }
#pragma unroll
    for (int o = 16; o > 0; o >>= 1) sum += __shfl_xor_sync(0xffffffffu, sum, o);
    const float rinv = 1.0f / sum;

    // ---- R = beta @ Hsh, Hsh tiled through smem (shared by 8 warps) ----
    float4 racc = make_float4(0.f, 0.f, 0.f, 0.f);
    for (int st = 0; st < 16; ++st) {
        __syncthreads();
#pragma unroll
        for (int i = 0; i < 16; ++i) {
            int id = i * 256 + tid;
            int s = id >> 7, h = id & 127;
            tile[s * 128 + h] = Hsh[boff + (size_t)(st * 32 + s) * HID + h];
        }
        __syncthreads();
#pragma unroll 4
        for (int s = 0; s < 32; ++s) {
            const float ws = sc[wid * 512 + st * 32 + s];
            const float4 hv = *(const float4*)&tile[s * 128 + lane * 4];
            racc.x = fmaf(ws, hv.x, racc.x);
            racc.y = fmaf(ws, hv.y, racc.y);
            racc.z = fmaf(ws, hv.z, racc.z);
            racc.w = fmaf(ws, hv.w, racc.w);
        }
    }
    racc.x *= rinv; racc.y *= rinv; racc.z *= rinv; racc.w *= rinv;
    *(float4*)&R[boff + (size_t)(t0 + wid) * HID + lane * 4] = racc;
}

// ============================================================================
extern "C" void kernel_launch(void* const* d_in, const int* in_sizes, int n_in,
                              void* d_out, int out_size)
{
    const float* x       = (const float*)d_in[0];
    const float* Wih_s   = (const float*)d_in[1];
    const float* Whh_s   = (const float*)d_in[2];
    const float* b_s     = (const float*)d_in[3];
    const float* Wx      = (const float*)d_in[4];
    const float* Wht     = (const float*)d_in[5];
    const float* Whs     = (const float*)d_in[6];
    const float* bs      = (const float*)d_in[7];
    const float* u       = (const float*)d_in[8];
    // d_in[9] = bu: cancels in softmax, unused
    const float* Wih_t   = (const float*)d_in[10];
    const float* Whh_t   = (const float*)d_in[11];
    const float* b_t     = (const float*)d_in[12];
    float* out = (float*)d_out;

    float *xg, *Hsh, *A, *C, *R;
    cudaGetSymbolAddress((void**)&xg,  g_xg);
    cudaGetSymbolAddress((void**)&Hsh, g_Hsh);
    cudaGetSymbolAddress((void**)&A,   g_A);
    cudaGetSymbolAddress((void**)&C,   g_C);
    cudaGetSymbolAddress((void**)&R,   g_R);

    const float s2 = 2.0f * LOG2E;
    dim3 gN512(32, 8), gN128(32, 2);

    // 1) xg_s = x @ Wih_s^T + b_s
    gemm_kernel<<<gN512, 256>>>(x, Wih_s, nullptr, nullptr, b_s, xg, 512, 128, 1, 1.0f);
    // 2) shared LSTM
    lstm_kernel<<<8, 512>>>(xg, Whh_s, Hsh);
    // 3) A = 2L * (Hsh @ Wht)
    gemm_kernel<<<gN128, 256>>>(Hsh, Wht, nullptr, nullptr, nullptr, A, 128, 128, 0, s2);
    // 4) C = 2L * (x @ Wx + Hsh @ Whs + bs)
    gemm_kernel<<<gN128, 256>>>(x, Wx, Hsh, Whs, bs, C, 128, 128, 0, s2);
    // 5) fused scores/softmax/R
    attn_kernel<<<256, 256>>>(A, C, Hsh, u, R);
    // 6) xg_t = x @ Wih_t[:, :128]^T + R @ Wih_t[:, 128:]^T + b_t
    gemm_kernel<<<gN512, 256>>>(x, Wih_t, R, Wih_t + 128, b_t, xg, 512, 256, 1, 1.0f);
    // 7) task LSTM -> output
    lstm_kernel<<<8, 512>>>(xg, Whh_t, out);
}

// round 12
// speedup vs baseline: 1.0343x; 1.0343x over previous
#include <cuda_runtime.h>
#include <cstdint>

#define BATCH 4
#define TSEQ  512
#define HID   128
#define LOG2E 1.4426950408889634f

// ---------------- scratch (no allocation allowed) ---------------------------
__device__ float g_xg [BATCH * TSEQ * 4 * HID];   // reused by both LSTMs
__device__ float g_Hsh[BATCH * TSEQ * HID];
__device__ float g_A  [BATCH * TSEQ * HID];
__device__ float g_C  [BATCH * TSEQ * HID];
__device__ float g_R  [BATCH * TSEQ * HID];

// ---------------- helpers ----------------------------------------------------
__device__ __forceinline__ float ex2f(float x){ float y; asm("ex2.approx.f32 %0, %1;" : "=f"(y) : "f"(x)); return y; }
__device__ __forceinline__ float rcpf(float x){ float y; asm("rcp.approx.f32 %0, %1;" : "=f"(y) : "f"(x)); return y; }
__device__ __forceinline__ float tanha(float x){ float y; asm("tanh.approx.f32 %0, %1;" : "=f"(y) : "f"(x)); return y; }
__device__ __forceinline__ float sigf(float x){ return rcpf(1.0f + ex2f(-LOG2E * x)); }
__device__ __forceinline__ float tanhf_fast(float x){
    return fmaf(-2.0f, rcpf(1.0f + ex2f(2.0f * LOG2E * x)), 1.0f);
}
__device__ __forceinline__ double fma2(double a, double b, double c){
    double d; asm("fma.rn.f32x2 %0, %1, %2, %3;" : "=d"(d) : "d"(a), "d"(b), "d"(c)); return d;
}
__device__ __forceinline__ uint32_t smem_u32(const void* p){
    uint32_t a; asm("{ .reg .u64 t; cvta.to.shared.u64 t, %1; cvt.u32.u64 %0, t; }" : "=r"(a) : "l"(p)); return a;
}
__device__ __forceinline__ uint32_t mapa32(uint32_t a, uint32_t r){
    uint32_t d; asm("mapa.shared::cluster.u32 %0, %1, %2;" : "=r"(d) : "r"(a), "r"(r)); return d;
}
__device__ __forceinline__ uint32_t ctarank(){
    uint32_t r; asm("mov.u32 %0, %%cluster_ctarank;" : "=r"(r)); return r;
}
__device__ __forceinline__ void mbar_init(uint32_t a, uint32_t cnt){
    asm volatile("mbarrier.init.shared.b64 [%0], %1;" :: "r"(a), "r"(cnt) : "memory");
}
__device__ __forceinline__ void mbar_expect(uint32_t a, uint32_t tx){
    asm volatile("mbarrier.arrive.expect_tx.shared.b64 _, [%0], %1;" :: "r"(a), "r"(tx) : "memory");
}
__device__ __forceinline__ void mbar_wait(uint32_t mb, uint32_t phase){
    asm volatile(
        "{\n\t.reg .pred P;\n\t"
        "W_%=:\n\t"
        "mbarrier.try_wait.parity.acquire.cluster.shared::cta.b64 P, [%0], %1, 0x989680;\n\t"
        "@P bra.uni D_%=;\n\t"
        "bra.uni W_%=;\n\t"
        "D_%=:\n\t}"
        :: "r"(mb), "r"(phase) : "memory");
}
__device__ __forceinline__ void st_async32(uint32_t daddr, uint32_t dmbar, float v){
    asm volatile("st.async.shared::cluster.mbarrier::complete_tx::bytes.b32 [%0], %1, [%2];"
        :: "r"(daddr), "r"(__float_as_uint(v)), "r"(dmbar) : "memory");
}
__device__ __forceinline__ void cluster_sync_(){
    asm volatile("barrier.cluster.arrive.aligned;" ::: "memory");
    asm volatile("barrier.cluster.wait.aligned;" ::: "memory");
}

// ============================================================================
// LSTM: 2-CTA cluster per batch. CTA rank owns hidden units [64r, 64r+64)
// (all 4 gates = 256 weight rows, register-resident, f32x2 math).
// Split-readiness protocol: per buffer there are TWO tx-mbarriers,
// own[wb] (fed by the 64 LOCAL update-thread st.asyncs, 256B) and
// peer[wb] (fed by the 64 REMOTE st.asyncs, 256B). Each thread's 64 weight
// columns are reordered [own-rank 32 | peer-rank 32], so the own-half dot
// starts as soon as local h lands and OVERLAPS the ~215-cyc DSMEM transit
// of the peer half. One __syncthreads per step.
// ============================================================================
__global__ __cluster_dims__(2,1,1) __launch_bounds__(512,1)
void lstm_kernel(const float* __restrict__ xg,   // [B,T,512] (bias pre-added)
                 const float* __restrict__ Whh,  // [512,128]
                 float* __restrict__ Hout)       // [B,T,128]
{
    __shared__ __align__(16) float hsm[2][HID];
    __shared__ __align__(16) float gsm[2][256];
    __shared__ __align__(8) unsigned long long mbar[4];  // own0,own1,peer0,peer1

    const int tid  = threadIdx.x;
    const int b    = blockIdx.x >> 1;
    const uint32_t rank = ctarank();
    const int rk   = (int)rank;
    const int row_l = tid >> 1;          // 0..255 local row
    const int half  = tid & 1;           // which 32-col sub-slice per block
    const int q     = row_l >> 6;        // gate index (i,f,g,o)
    const int j     = row_l & 63;        // local unit
    const int grow  = q * 128 + rk * 64 + j;   // row in [0,512)

    // 64 weight floats as 32 f32x2 pairs, reordered [own 32 cols | peer 32]
    double w[32];
    const float* wrow = Whh + (size_t)grow * HID;
    const double* wpo = (const double*)(wrow + rk * 64 + half * 32);
    const double* wpp = (const double*)(wrow + (rk ^ 1) * 64 + half * 32);
#pragma unroll
    for (int i = 0; i < 16; ++i) { w[i] = wpo[i]; w[16 + i] = wpp[i]; }

    if (tid < HID) { hsm[0][tid] = 0.0f; hsm[1][tid] = 0.0f; }

    const uint32_t mb = smem_u32(&mbar[0]);
    const uint32_t hb = smem_u32(&hsm[0][0]);
    if (tid == 0) {
#pragma unroll
        for (int i = 0; i < 4; ++i) mbar_init(mb + 8u * i, 1);
        asm volatile("fence.mbarrier_init.release.cluster;" ::: "memory");
#pragma unroll
        for (int i = 0; i < 4; ++i) mbar_expect(mb + 8u * i, 256);
    }
    __syncthreads();
    cluster_sync_();   // all inits visible before any st.async lands

    const int gu = rk * 64 + tid;                  // valid for tid<64
    uint32_t dh_s[2], dm_s[2], dh_p[2], dm_p[2];   // [buffer]
    if (tid < 64) {
#pragma unroll
        for (int wb = 0; wb < 2; ++wb) {
            dh_s[wb] = mapa32(hb + (uint32_t)(wb * HID + gu) * 4u, rank);
            dm_s[wb] = mapa32(mb + (uint32_t)wb * 8u, rank);            // own[wb] local
            dh_p[wb] = mapa32(hb + (uint32_t)(wb * HID + gu) * 4u, rank ^ 1u);
            dm_p[wb] = mapa32(mb + 16u + (uint32_t)wb * 8u, rank ^ 1u); // peer[wb] remote
        }
    }

    const float* xb = xg + (size_t)b * TSEQ * 512;
    float xv = 0.0f, nv = 0.0f;
    if (!half) xv = __ldg(xb + grow);              // step-0 input projection
    float c = 0.0f;
    int po0 = 0, po1 = 0, pp0 = 0, pp1 = 0;        // phases: own[0/1], peer[0/1]

    for (int t = 0; t < TSEQ; ++t) {
        if (!half && t + 1 < TSEQ)                  // prefetch next xg
            nv = __ldg(xb + (size_t)(t + 1) * 512 + grow);

        const int par = t & 1;
        double a0 = 0.0, a1 = 0.0;

        // ---- own half: ready almost immediately (local st.async) ----
        if (t > 0) {
            const uint32_t mo = mb + (uint32_t)par * 8u;
            mbar_wait(mo, par ? (uint32_t)po1 : (uint32_t)po0);
            if (par) po1 ^= 1; else po0 ^= 1;
            if (tid == 0) mbar_expect(mo, 256);     // re-arm for step t+2
        }
        {
            const double2* hp = (const double2*)(&hsm[par][rk * 64 + half * 32]);
#pragma unroll
            for (int i = 0; i < 8; ++i) {
                const double2 hv = hp[i];
                a0 = fma2(w[2 * i],     hv.x, a0);
                a1 = fma2(w[2 * i + 1], hv.y, a1);
            }
        }
        // ---- peer half: DSMEM transit overlapped with the own-half dot ----
        if (t > 0) {
            const uint32_t mp = mb + 16u + (uint32_t)par * 8u;
            mbar_wait(mp, par ? (uint32_t)pp1 : (uint32_t)pp0);
            if (par) pp1 ^= 1; else pp0 ^= 1;
            if (tid == 0) mbar_expect(mp, 256);
        }
        {
            const double2* hp = (const double2*)(&hsm[par][(rk ^ 1) * 64 + half * 32]);
#pragma unroll
            for (int i = 0; i < 8; ++i) {
                const double2 hv = hp[i];
                a0 = fma2(w[16 + 2 * i],     hv.x, a0);
                a1 = fma2(w[16 + 2 * i + 1], hv.y, a1);
            }
        }

        long long l0 = __double_as_longlong(a0), l1 = __double_as_longlong(a1);
        float s = (__uint_as_float((unsigned)l0) + __uint_as_float((unsigned)(l0 >> 32)))
                + (__uint_as_float((unsigned)l1) + __uint_as_float((unsigned)(l1 >> 32)));
        s += __shfl_xor_sync(0xffffffffu, s, 1);    // combine the two sub-slices
        if (!half) gsm[par][row_l] = s + xv;        // xg folded in here
        __syncthreads();

        if (tid < 64) {
            const float gi = gsm[par][tid];
            const float gf = gsm[par][64 + tid];
            const float gg = gsm[par][128 + tid];
            const float go = gsm[par][192 + tid];
            c = sigf(gf) * c + sigf(gi) * tanhf_fast(gg);
            const float h = sigf(go) * tanhf_fast(c);
            Hout[((size_t)b * TSEQ + t) * HID + gu] = h;
            if (t + 1 < TSEQ) {
                const int wb = par ^ 1;
                st_async32(dh_s[wb], dm_s[wb], h);   // self  -> own[wb]
                st_async32(dh_p[wb], dm_p[wb], h);   // peer  -> peer[wb] (remote)
            }
        }
        xv = nv;
    }
    cluster_sync_();   // no early exit while peer st.async may be in flight
}

// ============================================================================
// Generic tiled GEMM body (K fixed = 128 per operand pair):
//   C[M,N] = scale * (A1@B1 (+ A2@B2) + bias)
// bt=1: B stored [N,K] row-major (x @ W^T); bt=0: B stored [K,N].
// ============================================================================
__device__ __forceinline__ void gemm_body(
    const float* __restrict__ A1, const float* __restrict__ B1,
    const float* __restrict__ A2, const float* __restrict__ B2,
    const float* __restrict__ bias, float* __restrict__ Co,
    int N, int ldb, int bt, float scale)
{
    __shared__ float As[16][68];
    __shared__ float Bs[16][68];
    const int tid = threadIdx.x;
    const int m0 = blockIdx.x * 64;
    const int n0 = blockIdx.y * 64;
    const int tx = tid & 15, ty = tid >> 4;

    float acc[4][4];
#pragma unroll
    for (int i = 0; i < 4; ++i)
#pragma unroll
        for (int jj = 0; jj < 4; ++jj) acc[i][jj] = 0.0f;

    for (int pair = 0; pair < 2; ++pair) {
        const float* A = pair ? A2 : A1;
        const float* B = pair ? B2 : B1;
        if (A == nullptr) break;
        for (int kc = 0; kc < 128; kc += 16) {
#pragma unroll
            for (int i = 0; i < 4; ++i) {
                int id = i * 256 + tid;
                int k = id & 15, m = id >> 4;
                As[k][m] = A[(size_t)(m0 + m) * 128 + kc + k];
            }
#pragma unroll
            for (int i = 0; i < 4; ++i) {
                int id = i * 256 + tid;
                if (bt) { int k = id & 15, n = id >> 4;
                    Bs[k][n] = B[(size_t)(n0 + n) * ldb + kc + k];
                } else {  int n = id & 63, k = id >> 6;
                    Bs[k][n] = B[(size_t)(kc + k) * ldb + n0 + n];
                }
            }
            __syncthreads();
#pragma unroll
            for (int k = 0; k < 16; ++k) {
                float av[4], bv[4];
#pragma unroll
                for (int i = 0; i < 4; ++i) av[i] = As[k][ty * 4 + i];
#pragma unroll
                for (int jj = 0; jj < 4; ++jj) bv[jj] = Bs[k][tx * 4 + jj];
#pragma unroll
                for (int i = 0; i < 4; ++i)
#pragma unroll
                    for (int jj = 0; jj < 4; ++jj)
                        acc[i][jj] = fmaf(av[i], bv[jj], acc[i][jj]);
            }
            __syncthreads();
        }
    }
#pragma unroll
    for (int i = 0; i < 4; ++i) {
        const size_t ro = (size_t)(m0 + ty * 4 + i) * N + n0 + tx * 4;
#pragma unroll
        for (int jj = 0; jj < 4; ++jj) {
            float bv = bias ? bias[n0 + tx * 4 + jj] : 0.0f;
            Co[ro + jj] = scale * (acc[i][jj] + bv);
        }
    }
}

__global__ void __launch_bounds__(256)
gemm_kernel(const float* __restrict__ A1, const float* __restrict__ B1,
            const float* __restrict__ A2, const float* __restrict__ B2,
            const float* __restrict__ bias, float* __restrict__ Co,
            int N, int ldb, int bt, float scale)
{
    gemm_body(A1, B1, A2, B2, bias, Co, N, ldb, bt, scale);
}

// Fused attention projections (one launch, blockIdx.z selects output):
//   z=0: A = Hsh @ Wht          z=1: C = x @ Wx + Hsh @ Whs + bs
__global__ void __launch_bounds__(256)
gemm34_kernel(const float* __restrict__ Hsh, const float* __restrict__ Wht,
              const float* __restrict__ x,   const float* __restrict__ Wx,
              const float* __restrict__ Whs, const float* __restrict__ bs,
              float* __restrict__ A, float* __restrict__ C)
{
    if (blockIdx.z == 0)
        gemm_body(Hsh, Wht, nullptr, nullptr, nullptr, A, 128, 128, 0, 1.0f);
    else
        gemm_body(x, Wx, Hsh, Whs, bs, C, 128, 128, 0, 1.0f);
}

// ============================================================================
// Attention: scores -> softmax -> R, fused. Block = (batch, 8 t-rows),
// 256 threads (warp w <-> t-row). score[t,s] = sum_h u[h]*tanh(A[t,h]+C[s,h])
// via MUFU.TANH (bu cancels in softmax over s).
// ============================================================================
__global__ void __launch_bounds__(256)
attn_kernel(const float* __restrict__ Ax, const float* __restrict__ Cx,
            const float* __restrict__ Hsh, const float* __restrict__ u,
            float* __restrict__ R)
{
    __shared__ float Asm[8 * 128];
    __shared__ float usm[128];
    __shared__ __align__(16) float tile[32 * 129];
    __shared__ float sc[8 * 512];

    const int tid = threadIdx.x;
    const int wid = tid >> 5, lane = tid & 31;
    const int b = blockIdx.x >> 6;
    const int t0 = (blockIdx.x & 63) * 8;
    const size_t boff = (size_t)b * TSEQ * HID;

#pragma unroll
    for (int i = 0; i < 4; ++i) {
        int id = i * 256 + tid;
        Asm[id] = Ax[boff + (size_t)(t0 + (id >> 7)) * HID + (id & 127)];
    }
    if (tid < 128) usm[tid] = u[tid];
    __syncthreads();

    // ---- scores ----
    const float* arow = &Asm[wid * 128];
    for (int st = 0; st < 16; ++st) {
#pragma unroll
        for (int i = 0; i < 16; ++i) {
            int id = i * 256 + tid;
            int s = id >> 7, h = id & 127;
            tile[s * 129 + h] = Cx[boff + (size_t)(st * 32 + s) * HID + h];
        }
        __syncthreads();
        const float* crow = &tile[lane * 129];
        float su0 = 0.0f, su1 = 0.0f;
#pragma unroll 8
        for (int h = 0; h < 128; h += 2) {
            su0 = fmaf(usm[h],     tanha(arow[h]     + crow[h]),     su0);
            su1 = fmaf(usm[h + 1], tanha(arow[h + 1] + crow[h + 1]), su1);
        }
        sc[wid * 512 + st * 32 + lane] = su0 + su1;
        __syncthreads();
    }

    // ---- softmax (per warp over its private t-row) ----
    float m = -1e30f;
#pragma unroll
    for (int i = 0; i < 16; ++i) m = fmaxf(m, sc[wid * 512 + i * 32 + lane]);
#pragma unroll
    for (int o = 16; o > 0; o >>= 1) m = fmaxf(m, __shfl_xor_sync(0xffffffffu, m, o));
    float sum = 0.0f;
#pragma unroll
    for (int i = 0; i < 16; ++i) {
        int idx = wid * 512 + i * 32 + lane;
        float e = ex2f(LOG2E * (sc[idx] - m));
        sc[idx] = e; sum += e;
    }
#pragma unroll
    for (int o = 16; o > 0; o >>= 1) sum += __shfl_xor_sync(0xffffffffu, sum, o);
    const float rinv = 1.0f / sum;

    // ---- R = beta @ Hsh, Hsh tiled through smem (shared by 8 warps) ----
    float4 racc = make_float4(0.f, 0.f, 0.f, 0.f);
    for (int st = 0; st < 16; ++st) {
        __syncthreads();
#pragma unroll
        for (int i = 0; i < 16; ++i) {
            int id = i * 256 + tid;
            int s = id >> 7, h = id & 127;
            tile[s * 128 + h] = Hsh[boff + (size_t)(st * 32 + s) * HID + h];
        }
        __syncthreads();
#pragma unroll 4
        for (int s = 0; s < 32; ++s) {
            const float ws = sc[wid * 512 + st * 32 + s];
            const float4 hv = *(const float4*)&tile[s * 128 + lane * 4];
            racc.x = fmaf(ws, hv.x, racc.x);
            racc.y = fmaf(ws, hv.y, racc.y);
            racc.z = fmaf(ws, hv.z, racc.z);
            racc.w = fmaf(ws, hv.w, racc.w);
        }
    }
    racc.x *= rinv; racc.y *= rinv; racc.z *= rinv; racc.w *= rinv;
    *(float4*)&R[boff + (size_t)(t0 + wid) * HID + lane * 4] = racc;
}

// ============================================================================
extern "C" void kernel_launch(void* const* d_in, const int* in_sizes, int n_in,
                              void* d_out, int out_size)
{
    const float* x       = (const float*)d_in[0];
    const float* Wih_s   = (const float*)d_in[1];
    const float* Whh_s   = (const float*)d_in[2];
    const float* b_s     = (const float*)d_in[3];
    const float* Wx      = (const float*)d_in[4];
    const float* Wht     = (const float*)d_in[5];
    const float* Whs     = (const float*)d_in[6];
    const float* bs      = (const float*)d_in[7];
    const float* u       = (const float*)d_in[8];
    // d_in[9] = bu: cancels in softmax, unused
    const float* Wih_t   = (const float*)d_in[10];
    const float* Whh_t   = (const float*)d_in[11];
    const float* b_t     = (const float*)d_in[12];
    float* out = (float*)d_out;

    float *xg, *Hsh, *A, *C, *R;
    cudaGetSymbolAddress((void**)&xg,  g_xg);
    cudaGetSymbolAddress((void**)&Hsh, g_Hsh);
    cudaGetSymbolAddress((void**)&A,   g_A);
    cudaGetSymbolAddress((void**)&C,   g_C);
    cudaGetSymbolAddress((void**)&R,   g_R);

    dim3 gN512(32, 8), g34(32, 2, 2);

    // 1) xg_s = x @ Wih_s^T + b_s
    gemm_kernel<<<gN512, 256>>>(x, Wih_s, nullptr, nullptr, b_s, xg, 512, 128, 1, 1.0f);
    // 2) shared LSTM
    lstm_kernel<<<8, 512>>>(xg, Whh_s, Hsh);
    // 3+4 fused) A = Hsh @ Wht ; C = x @ Wx + Hsh @ Whs + bs
    gemm34_kernel<<<g34, 256>>>(Hsh, Wht, x, Wx, Whs, bs, A, C);
    // 5) fused scores/softmax/R
    attn_kernel<<<256, 256>>>(A, C, Hsh, u, R);
    // 6) xg_t = x @ Wih_t[:, :128]^T + R @ Wih_t[:, 128:]^T + b_t
    gemm_kernel<<<gN512, 256>>>(x, Wih_t, R, Wih_t + 128, b_t, xg, 512, 256, 1, 1.0f);
    // 7) task LSTM -> output
    lstm_kernel<<<8, 512>>>(xg, Whh_t, out);
}